// round 7
// baseline (speedup 1.0000x reference)
#include <cuda_runtime.h>
#include <cuda_fp16.h>
#include <cstdint>

// ---------------- problem constants -------------------------------------------
#define NVEC   131072          // 16*1024*8 vectors
#define KC     2048            // codebook size
#define DDIM   64              // codebook_dim
#define CODES_ELEMS 8388608
#define GATHER_BLOCKS 8192

// GEMM tiling (mma.sync m16n8k16 fp16, 3-term split => K expanded to 192)
#define MT      128            // rows per CTA
#define NCH     128            // codes per chunk
#define NCHUNKS (KC / NCH)     // 16
#define KE      192            // [Ah|Al|Ah] x [Bh|Bh|Bl]
#define LDH     200            // row stride in halves (400B)

// smem layout (bytes)
#define SA_OFF    0
#define SA_BYTES  (MT * LDH * 2)             // 51200
#define SB_OFF    (SA_OFF + SA_BYTES)
#define SB_BYTES  (NCH * LDH * 2)            // 51200 per buffer, x2
#define SBIAS_OFF (SB_OFF + 2 * SB_BYTES)    // 153600
#define SMEM_TOTAL (SBIAS_OFF + KC * 4)      // 161792

// ---------------- device scratch ----------------------------------------------
__device__ __align__(16) __half cb_hi_g[KC * DDIM];
__device__ __align__(16) __half cb_lo_g[KC * DDIM];
__device__ __align__(16) float  cbias_g[KC];
__device__ int   idx_g[NVEC];
__device__ int   idx2_g[NVEC];
__device__ float bsum_g[GATHER_BLOCKS];

// ---------------- helpers -------------------------------------------------------
__device__ __forceinline__ uint32_t smem_u32(const void* p) {
    uint32_t a;
    asm("{ .reg .u64 t; cvta.to.shared.u64 t, %1; cvt.u32.u64 %0, t; }" : "=r"(a) : "l"(p));
    return a;
}
__device__ __forceinline__ void cp16(uint32_t dst, const void* src) {
    asm volatile("cp.async.cg.shared.global [%0], [%1], 16;" :: "r"(dst), "l"(src) : "memory");
}
#define CP_COMMIT() asm volatile("cp.async.commit_group;" ::: "memory")
#define CP_WAIT0()  asm volatile("cp.async.wait_group 0;" ::: "memory")
#define CP_WAIT1()  asm volatile("cp.async.wait_group 1;" ::: "memory")

__device__ __forceinline__ void mma_f16(float& d0, float& d1, float& d2, float& d3,
                                        uint32_t a0, uint32_t a1, uint32_t a2, uint32_t a3,
                                        uint32_t b0, uint32_t b1) {
    asm volatile(
        "mma.sync.aligned.m16n8k16.row.col.f32.f16.f16.f32 "
        "{%0,%1,%2,%3}, {%4,%5,%6,%7}, {%8,%9}, {%0,%1,%2,%3};"
        : "+f"(d0), "+f"(d1), "+f"(d2), "+f"(d3)
        : "r"(a0), "r"(a1), "r"(a2), "r"(a3), "r"(b0), "r"(b1));
}

// merge another top-2 pair (o1,oi1,o2,oi2) into (b1,i1,b2,i2).
// "better" = higher score, ties -> lower index.
__device__ __forceinline__ void merge2(float& b1, int& i1, float& b2, int& i2,
                                       float o1, int oi1, float o2, int oi2) {
    bool t1 = (o1 > b1) || (o1 == b1 && oi1 < i1);
    if (t1) {
        bool t2 = (b1 > o2) || (b1 == o2 && i1 < oi2);
        float nb2 = t2 ? b1 : o2; int ni2 = t2 ? i1 : oi2;
        b1 = o1; i1 = oi1; b2 = nb2; i2 = ni2;
    } else {
        bool t2 = (o1 > b2) || (o1 == b2 && oi1 < i2);
        if (t2) { b2 = o1; i2 = oi1; }
    }
}

// ---------------- kernel 0: codebook split + bias -------------------------------
__global__ __launch_bounds__(256) void split_cb_kernel(const float* __restrict__ cb) {
    int k = blockIdx.x * 256 + threadIdx.x;
    if (k >= KC) return;
    float s = 0.f;
#pragma unroll
    for (int d = 0; d < DDIM; d++) {
        float v = cb[k * DDIM + d];
        s += v * v;
        __half h = __float2half_rn(v);
        cb_hi_g[k * DDIM + d] = h;
        cb_lo_g[k * DDIM + d] = __float2half_rn(v - __half2float(h));
    }
    cbias_g[k] = 0.5f * s;
}

// ---------------- B chunk loader: [Bh(0:64) | Bh(64:128) | Bl(128:192)] ---------
__device__ __forceinline__ void load_B(int ch, uint32_t sb_buf, int tid) {
#pragma unroll
    for (int it = 0; it < 12; it++) {
        int i = it * 256 + tid;              // 0..3071 = 128 rows * 24 segs
        int r = i / 24, seg = i % 24;
        int code = ch * NCH + r;
        const __half* src;
        int dcol;
        if (seg < 8)       { src = &cb_hi_g[code * DDIM + seg * 8];        dcol = seg * 8; }
        else if (seg < 16) { src = &cb_hi_g[code * DDIM + (seg - 8) * 8];  dcol = 64 + (seg - 8) * 8; }
        else               { src = &cb_lo_g[code * DDIM + (seg - 16) * 8]; dcol = 128 + (seg - 16) * 8; }
        cp16(sb_buf + (r * LDH + dcol) * 2, src);
    }
}

// ---------------- kernel 1: fp16x3 tensor scores + per-row top-2 ----------------
__global__ __launch_bounds__(256, 1)
void argmin_mma_kernel(const float* __restrict__ z) {
    extern __shared__ __align__(16) char smem[];
    __half* As = (__half*)(smem + SA_OFF);
    float*  bias_sm = (float*)(smem + SBIAS_OFF);
    uint32_t sbase = smem_u32(smem);

    const int tid = threadIdx.x;
    const int wid = tid >> 5;
    const int lane = tid & 31;
    const int g = lane >> 2;                 // group row 0..7
    const int t = lane & 3;                  // thread-in-group 0..3
    const int wm = (wid >> 2) * 64;          // warp M offset (0 / 64)
    const int stripe = wid & 3;
    const int wn = stripe * 32;              // warp N offset (0/32/64/96)
    const int m0 = blockIdx.x * MT;

    // ---- prologue: stage raw z tile (fp32) into B buffer 0 + load bias ----
    {
        const float* zsrc = z + (long)m0 * DDIM;
#pragma unroll
        for (int it = 0; it < 8; it++) {
            int i = it * 256 + tid;          // 2048 x float4
            cp16(sbase + SB_OFF + i * 16, zsrc + i * 4);
        }
#pragma unroll
        for (int it = 0; it < 2; it++) {
            int i = it * 256 + tid;          // 512 x float4
            cp16(sbase + SBIAS_OFF + i * 16, cbias_g + i * 4);
        }
        CP_COMMIT();
        CP_WAIT0();
        __syncthreads();
        // convert: A = [Ah | Al | Ah], row stride LDH halves
        const float* stage = (const float*)(smem + SB_OFF);
#pragma unroll
        for (int it = 0; it < 32; it++) {
            int e = it * 256 + tid;          // 8192 elements
            int m = e >> 6, k = e & 63;
            float x = stage[e];
            __half h = __float2half_rn(x);
            __half l = __float2half_rn(x - __half2float(h));
            As[m * LDH + k]       = h;
            As[m * LDH + 64 + k]  = l;
            As[m * LDH + 128 + k] = h;
        }
        __syncthreads();
        load_B(0, sbase + SB_OFF, tid);             CP_COMMIT();
        load_B(1, sbase + SB_OFF + SB_BYTES, tid);  CP_COMMIT();
        CP_WAIT1();                                  // B0 landed
        __syncthreads();
    }

    float b1v[8], b2v[8];
    int   b1i[8], b2i[8];
#pragma unroll
    for (int s = 0; s < 8; s++) {
        b1v[s] = -3.4e38f; b1i[s] = 0;
        b2v[s] = -3.4e38f; b2i[s] = 1;
    }

#pragma unroll 1
    for (int ch = 0; ch < NCHUNKS; ch++) {
        const __half* Bb = (const __half*)(smem + SB_OFF + (ch & 1) * SB_BYTES);
        const uint32_t sb_buf = sbase + SB_OFF + (ch & 1) * SB_BYTES;

        // ---- accumulators, bias folded in (score = z.c - 0.5||c||^2) ----
        float C[4][4][4];
#pragma unroll
        for (int ni = 0; ni < 4; ni++) {
            float2 bv = *(const float2*)&bias_sm[ch * NCH + wn + ni * 8 + 2 * t];
#pragma unroll
            for (int mi = 0; mi < 4; mi++) {
                C[mi][ni][0] = -bv.x; C[mi][ni][1] = -bv.y;
                C[mi][ni][2] = -bv.x; C[mi][ni][3] = -bv.y;
            }
        }

        // ---- K=192 mma chain ----
#pragma unroll
        for (int ks = 0; ks < KE / 16; ks++) {
            uint32_t Af[4][4];
#pragma unroll
            for (int mi = 0; mi < 4; mi++) {
                const __half* ap = As + (wm + mi * 16 + g) * LDH + ks * 16 + 2 * t;
                Af[mi][0] = *(const uint32_t*)(ap);
                Af[mi][1] = *(const uint32_t*)(ap + 8 * LDH);
                Af[mi][2] = *(const uint32_t*)(ap + 8);
                Af[mi][3] = *(const uint32_t*)(ap + 8 * LDH + 8);
            }
#pragma unroll
            for (int ni = 0; ni < 4; ni++) {
                const __half* bp = Bb + (wn + ni * 8 + g) * LDH + ks * 16 + 2 * t;
                uint32_t b0 = *(const uint32_t*)(bp);
                uint32_t b1 = *(const uint32_t*)(bp + 8);
#pragma unroll
                for (int mi = 0; mi < 4; mi++)
                    mma_f16(C[mi][ni][0], C[mi][ni][1], C[mi][ni][2], C[mi][ni][3],
                            Af[mi][0], Af[mi][1], Af[mi][2], Af[mi][3], b0, b1);
            }
        }

        // ---- fold into running top-2 (ascending code order; strict > keeps lower idx)
#pragma unroll
        for (int ni = 0; ni < 4; ni++) {
            int c0 = ch * NCH + wn + ni * 8 + 2 * t;
#pragma unroll
            for (int mi = 0; mi < 4; mi++) {
#pragma unroll
                for (int hw = 0; hw < 2; hw++) {       // half-row within frag
                    int s = 2 * mi + hw;
#pragma unroll
                    for (int cc = 0; cc < 2; cc++) {   // the 2 adjacent columns
                        float v = C[mi][ni][hw * 2 + cc];
                        int   ci = c0 + cc;
                        if (v > b1v[s])      { b2v[s] = b1v[s]; b2i[s] = b1i[s];
                                               b1v[s] = v;      b1i[s] = ci; }
                        else if (v > b2v[s]) { b2v[s] = v;      b2i[s] = ci; }
                    }
                }
            }
        }

        __syncthreads();                       // all warps done reading this buffer
        if (ch + 2 < NCHUNKS) {
            load_B(ch + 2, sb_buf, tid);       // refill the buffer just consumed
            CP_COMMIT();
            CP_WAIT1();                        // previous in-flight chunk (ch+1) landed
        } else if (ch + 1 < NCHUNKS) {
            CP_WAIT0();
        }
        __syncthreads();
    }

    // ---- cross-warp top-2 combine --------------------------------------------
    float4* red = (float4*)(smem + SB_OFF);    // [MT rows][4 stripes] x float4
#pragma unroll
    for (int s = 0; s < 8; s++) {
        float v1 = b1v[s], v2 = b2v[s];
        int   i1 = b1i[s], i2 = b2i[s];
#pragma unroll
        for (int off = 1; off <= 2; off <<= 1) {
            float o1 = __shfl_xor_sync(0xffffffffu, v1, off);
            int  oi1 = __shfl_xor_sync(0xffffffffu, i1, off);
            float o2 = __shfl_xor_sync(0xffffffffu, v2, off);
            int  oi2 = __shfl_xor_sync(0xffffffffu, i2, off);
            merge2(v1, i1, v2, i2, o1, oi1, o2, oi2);
        }
        if (t == 0) {
            int mi = s >> 1, hw = s & 1;
            int row_local = wm + mi * 16 + hw * 8 + g;
            red[row_local * 4 + stripe] =
                make_float4(v1, __int_as_float(i1), v2, __int_as_float(i2));
        }
    }
    __syncthreads();
    if (tid < MT) {
        float4 p = red[tid * 4];
        float v1 = p.x, v2 = p.z;
        int   i1 = __float_as_int(p.y), i2 = __float_as_int(p.w);
#pragma unroll
        for (int st = 1; st < 4; st++) {
            float4 q = red[tid * 4 + st];
            merge2(v1, i1, v2, i2, q.x, __float_as_int(q.y), q.z, __float_as_int(q.w));
        }
        int row = m0 + tid;
        idx_g[row]  = i1;
        idx2_g[row] = i2;
    }
}

// ---------------- kernel 2: exact fp32 rescore of top-2 + gather + loss ---------
__global__ __launch_bounds__(256)
void gather_kernel(const float* __restrict__ z, const float* __restrict__ cb,
                   float* __restrict__ codes_out, float* __restrict__ out_idx_f,
                   int write_codes, int write_idx) {
    const int tid = threadIdx.x;
    const int lin = blockIdx.x * 256 + tid;
    const int n = lin >> 4, d4 = lin & 15;
    const int i1 = idx_g[n], i2 = idx2_g[n];
    float4 c1 = *(const float4*)&cb[i1 * DDIM + d4 * 4];
    float4 c2 = *(const float4*)&cb[i2 * DDIM + d4 * 4];
    float4 zz = *(const float4*)&z[(long)n * DDIM + d4 * 4];

    float dx = c1.x - zz.x, dy = c1.y - zz.y, dz = c1.z - zz.z, dw = c1.w - zz.w;
    float s1 = dx * dx + dy * dy + dz * dz + dw * dw;
    dx = c2.x - zz.x; dy = c2.y - zz.y; dz = c2.z - zz.z; dw = c2.w - zz.w;
    float s2 = dx * dx + dy * dy + dz * dz + dw * dw;
#pragma unroll
    for (int off = 8; off; off >>= 1) {
        s1 += __shfl_xor_sync(0xffffffffu, s1, off);
        s2 += __shfl_xor_sync(0xffffffffu, s2, off);
    }
    const bool take2 = (s2 < s1) || (s2 == s1 && i2 < i1);
    if (write_codes) {
        float4 c = take2 ? c2 : c1;
        *(float4*)&codes_out[(long)n * DDIM + d4 * 4] = c;
    }
    __shared__ float ws[16];
    if (d4 == 0) {
        ws[tid >> 4] = take2 ? s2 : s1;
        if (write_idx) out_idx_f[n] = (float)(take2 ? i2 : i1);
    }
    __syncthreads();
    if (tid == 0) {
        float tt = 0.f;
#pragma unroll
        for (int i = 0; i < 16; i++) tt += ws[i];
        bsum_g[blockIdx.x] = tt;
    }
}

// ---------------- kernel 3: final loss reduction --------------------------------
__global__ __launch_bounds__(256)
void loss_kernel(float* __restrict__ out_loss, int write_loss) {
    __shared__ float sh[256];
    const int tid = threadIdx.x;
    float s = 0.f;
    for (int i = tid; i < GATHER_BLOCKS; i += 256) s += bsum_g[i];
    sh[tid] = s;
    __syncthreads();
    for (int off = 128; off; off >>= 1) {
        if (tid < off) sh[tid] += sh[tid + off];
        __syncthreads();
    }
    if (tid == 0 && write_loss)
        out_loss[0] = sh[0] * (1.0f / 8388608.0f);
}

// ---------------- launcher ------------------------------------------------------
extern "C" void kernel_launch(void* const* d_in, const int* in_sizes, int n_in,
                              void* d_out, int out_size) {
    const float* z  = (const float*)d_in[0];
    const float* cb = (const float*)d_in[1];
    if (n_in >= 2 && in_sizes[0] == KC * DDIM) { const float* t = z; z = cb; cb = t; }
    float* out = (float*)d_out;

    const long idx_off  = (long)CODES_ELEMS;
    const long loss_off = (long)CODES_ELEMS + NVEC;
    const int have_codes = out_size >= CODES_ELEMS;
    const int have_idx   = out_size >= CODES_ELEMS + NVEC;
    const int have_loss  = out_size >= CODES_ELEMS + NVEC + 1;

    cudaFuncSetAttribute(argmin_mma_kernel,
                         cudaFuncAttributeMaxDynamicSharedMemorySize, SMEM_TOTAL);

    split_cb_kernel<<<(KC + 255) / 256, 256>>>(cb);
    argmin_mma_kernel<<<NVEC / MT, 256, SMEM_TOTAL>>>(z);
    gather_kernel<<<GATHER_BLOCKS, 256>>>(z, cb, out, out + idx_off,
                                          have_codes, have_idx);
    loss_kernel<<<1, 256>>>(out + loss_off, have_loss);
}